// round 9
// baseline (speedup 1.0000x reference)
#include <cuda_runtime.h>
#include <mma.h>

using namespace nvcuda;

// Problem constants
#define Bn   2
#define Sn   4096
#define Dn   768
#define Hn   12
#define DKn  64
#define Mn   (Bn * Sn)       // 8192 rows of the token matrix

// ---------------------------------------------------------------------------
// Scratch (allocation-free rule: __device__ globals)
// ---------------------------------------------------------------------------
__device__ float g_q[Bn * Hn * Sn * DKn];   // [b][h][s][d]
__device__ float g_k[Bn * Hn * Sn * DKn];
__device__ float g_v[Bn * Hn * Sn * DKn];
__device__ float g_ctx[Mn * Dn];            // [b][s][h*64+d] == [M][D] row-major

// TF32 round (rna) — explicit so both smem staging paths are consistent
__device__ __forceinline__ float t32(float x) {
    float y;
    asm("cvt.rna.tf32.f32 %0, %1;\n" : "=f"(y) : "f"(x));
    return y;
}

// ---------------------------------------------------------------------------
// Projection GEMM: C[m][n] = sum_k X[m][k] * W[n][k] + bias[n]
//   X: row-major [M x 768], W: row-major [768 x 768] (used as B^T via col_major frag)
// Block tile 128x64, K-step 32. 8 warps (4 along M x 2 along N), each 32x32.
// 2 barriers per K-iter: pre-STS (protects prior mma reads) + post-STS.
//
// Fused-QKV mode (fused=1): blockIdx.z in {0,1,2} selects (Wq,bq)->g_q,
// (Wk,bk)->g_k, (Wv,bv)->g_v. One launch, 3x blocks -> single wave tail.
// Output-proj mode (fused=0): W0/b0 used, src = g_ctx, out -> outp row-major.
// ---------------------------------------------------------------------------
__global__ __launch_bounds__(256) void proj_kernel(
    const float* __restrict__ Xp,
    const float* __restrict__ W0, const float* __restrict__ b0,
    const float* __restrict__ W1, const float* __restrict__ b1,
    const float* __restrict__ W2, const float* __restrict__ b2,
    float* __restrict__ outp, int fused)
{
    __shared__ __align__(16) float sm[9216];     // 36.8 KB, reused by epilogue
    float* As = sm;               // 128 x 36 (K-tile 32, pad 4)
    float* Ws = sm + 128 * 36;    // 64 x 36

    const int z = fused ? blockIdx.z : 3;
    const float* X    = fused ? Xp : g_ctx;
    const float* W    = (z == 0) ? W0 : (z == 1) ? W1 : (z == 2) ? W2 : W0;
    const float* bias = (z == 0) ? b0 : (z == 1) ? b1 : (z == 2) ? b2 : b0;

    const int m0 = blockIdx.y * 128;
    const int n0 = blockIdx.x * 64;
    const int tid = threadIdx.x;
    const int wid = tid >> 5;
    const int lane = tid & 31;
    const int wm = wid & 3;       // warp row group (32 rows)
    const int wn = wid >> 2;      // warp col group (32 cols)

    wmma::fragment<wmma::accumulator, 16, 16, 8, float> acc[2][2];
#pragma unroll
    for (int i = 0; i < 2; i++)
#pragma unroll
        for (int j = 0; j < 2; j++)
            wmma::fill_fragment(acc[i][j], 0.0f);

    for (int k0 = 0; k0 < Dn; k0 += 32) {
        // Batch all 6 LDGs into registers before the barrier (MLP, latency
        // overlaps the barrier wait), then convert+STS after it.
        float4 av[4], wv[2];
#pragma unroll
        for (int t = 0; t < 4; t++) {
            int idx = tid + t * 256;
            int r = idx >> 3, kq = idx & 7;
            av[t] = *(const float4*)(X + (size_t)(m0 + r) * Dn + k0 + kq * 4);
        }
#pragma unroll
        for (int t = 0; t < 2; t++) {
            int idx = tid + t * 256;
            int r = idx >> 3, kq = idx & 7;
            wv[t] = *(const float4*)(W + (size_t)(n0 + r) * Dn + k0 + kq * 4);
        }
        __syncthreads();                         // prior iter's mma reads done
#pragma unroll
        for (int t = 0; t < 4; t++) {
            int idx = tid + t * 256;
            int r = idx >> 3, kq = idx & 7;
            float* d = As + r * 36 + kq * 4;
            d[0] = t32(av[t].x); d[1] = t32(av[t].y); d[2] = t32(av[t].z); d[3] = t32(av[t].w);
        }
#pragma unroll
        for (int t = 0; t < 2; t++) {
            int idx = tid + t * 256;
            int r = idx >> 3, kq = idx & 7;
            float* d = Ws + r * 36 + kq * 4;
            d[0] = t32(wv[t].x); d[1] = t32(wv[t].y); d[2] = t32(wv[t].z); d[3] = t32(wv[t].w);
        }
        __syncthreads();                         // tiles visible

#pragma unroll
        for (int kk = 0; kk < 4; kk++) {
            wmma::fragment<wmma::matrix_a, 16, 16, 8, wmma::precision::tf32, wmma::row_major> a[2];
            wmma::fragment<wmma::matrix_b, 16, 16, 8, wmma::precision::tf32, wmma::col_major> b[2];
#pragma unroll
            for (int i = 0; i < 2; i++)
                wmma::load_matrix_sync(a[i], As + (wm * 32 + i * 16) * 36 + kk * 8, 36);
#pragma unroll
            for (int j = 0; j < 2; j++)
                wmma::load_matrix_sync(b[j], Ws + (wn * 32 + j * 16) * 36 + kk * 8, 36);
#pragma unroll
            for (int i = 0; i < 2; i++)
#pragma unroll
                for (int j = 0; j < 2; j++)
                    wmma::mma_sync(acc[i][j], a[i], b[j], acc[i][j]);
        }
        // no trailing barrier: next iteration's pre-STS sync provides it
    }

    // Epilogue: per-warp private 32x36 region of sm (disjoint; guard reuse)
    __syncthreads();
    float* csm = sm + wid * 32 * 36;
#pragma unroll
    for (int i = 0; i < 2; i++)
#pragma unroll
        for (int j = 0; j < 2; j++)
            wmma::store_matrix_sync(csm + (i * 16) * 36 + j * 16, acc[i][j], 36, wmma::mem_row_major);
    __syncwarp();

    const int gm_base = m0 + wm * 32;
    const int gn = n0 + wn * 32 + lane;           // lane-per-column -> coalesced
    const float bval = bias[gn];

    if (!fused) {
#pragma unroll 4
        for (int r = 0; r < 32; r++) {
            float val = csm[r * 36 + lane] + bval;
            outp[(size_t)(gm_base + r) * Dn + gn] = val;
        }
    } else {
        float* o = (z == 0) ? g_q : (z == 1) ? g_k : g_v;
        const int h = gn >> 6, d = gn & 63;       // 32-col slab never crosses a head
#pragma unroll 4
        for (int r = 0; r < 32; r++) {
            float val = csm[r * 36 + lane] + bval;
            int gm = gm_base + r;
            int b = gm >> 12, s = gm & 4095;
            o[(((size_t)b * Hn + h) * Sn + s) * DKn + d] = val;
        }
    }
}

// ---------------------------------------------------------------------------
// Flash attention: grid (S/128, B*H), block 256 (8 warps).
// Each block owns 128 query rows; iterates 64 KV tiles of 64.
// Warp w (0..7) owns rows [16w, 16w+16): its Q A-fragments, its S/P rows in
// smem. The softmax threads for row r (=16w+lane/2) live in warp w, so the
// whole S -> softmax -> P -> PV -> O-update pipeline is warp-local (no block
// syncs except around the shared K/V tile reload).
// smem = (64+64+128) x 68 floats = 69.6 KB.
// KV staging: all 8 LDGs batched into registers BEFORE the tile barrier so
// their latency overlaps the barrier wait; convert+STS after. Both K and V
// are stored row-major ([t][d], ld=68) with identical float4 STS patterns —
// no V transpose. S=QK^T uses a col_major B fragment over K (B[d][t] =
// Ksm[t*ld+d]); PV uses a row_major B fragment over V (B[t][d] =
// Vsm[t*ld+d]). Same operand matrices, cheaper staging.
// Softmax runs in the exp2 domain: Q is pre-scaled by (1/8)*log2(e), so
// probabilities are exp2f(s - m) with no per-element FMUL.
// ---------------------------------------------------------------------------
#define FL_QT 128                                 // queries per block
#define FL_LD 68                                  // 64 + 4 pad (multiple of 4)
#define FL_SMEM_BYTES ((2 * 64 + FL_QT) * FL_LD * (int)sizeof(float))  // 69632
#define QSCALE (0.125f * 1.4426950408889634f)     // (1/sqrt(64)) * log2(e)

__global__ __launch_bounds__(256) void flash_kernel()
{
    extern __shared__ float dsm[];
    float* Ksm = dsm;                    // [64][68], K tile, row-major [t][d]
    float* Vsm = dsm + 64 * FL_LD;       // [64][68], V tile, row-major [t][d]
    float* Ssm = dsm + 2 * 64 * FL_LD;   // [128][68], Q staging / scores / P / PV

    const int bh = blockIdx.y;                       // b*H + h
    const size_t base = (size_t)bh * Sn * DKn;
    const float* Q = g_q + base;
    const float* K = g_k + base;
    const float* V = g_v + base;
    const int s0 = blockIdx.x * FL_QT;

    const int tid = threadIdx.x;
    const int w = tid >> 5;
    const int lane = tid & 31;
    const int r = w * 16 + (lane >> 1);              // local row 0..127 (warp-local)
    const int ch = lane & 1;                         // column half (32 cols each)

    // Staging-loop thread->element map (shared by K and V): 4 float4 per thread
    const int st_row = tid >> 2;                     // 0..63   (tid/4)
    const int st_cq0 = (tid & 3) * 4;                // 0,4,8,12 (float4 index base)

    // Stage Q (pre-scaled into the exp2 domain) into Ssm, then preload A-frags.
#pragma unroll
    for (int t = 0; t < 8; t++) {
        int idx = tid + t * 256;
        int row = idx >> 4, cq = idx & 15;
        float4 v4 = *(const float4*)(Q + (size_t)(s0 + row) * DKn + cq * 4);
        float* d = Ssm + row * FL_LD + cq * 4;
        d[0] = t32(v4.x * QSCALE); d[1] = t32(v4.y * QSCALE);
        d[2] = t32(v4.z * QSCALE); d[3] = t32(v4.w * QSCALE);
    }
    __syncthreads();

    wmma::fragment<wmma::matrix_a, 16, 16, 8, wmma::precision::tf32, wmma::row_major> qa[8];
#pragma unroll
    for (int kk = 0; kk < 8; kk++)
        wmma::load_matrix_sync(qa[kk], Ssm + (w * 16) * FL_LD + kk * 8, FL_LD);

    float m_run = -1e30f, l_run = 0.0f;              // m_run in log2 domain
    float O[32];
#pragma unroll
    for (int c = 0; c < 32; c++) O[c] = 0.0f;

    for (int j = 0; j < Sn / 64; j++) {
        const int t0 = j * 64;
        // --- Batched KV loads into registers (before the barrier) ---
        float4 kreg[4], vreg[4];
#pragma unroll
        for (int t = 0; t < 4; t++) {
            kreg[t] = *(const float4*)(K + (size_t)(t0 + st_row) * DKn + (st_cq0 + t) * 4);
            vreg[t] = *(const float4*)(V + (size_t)(t0 + st_row) * DKn + (st_cq0 + t) * 4);
        }
        __syncthreads();   // everyone done reading prior Ksm/Vsm (and iter-0 Q)
#pragma unroll
        for (int t = 0; t < 4; t++) {
            const int cq = st_cq0 + t;
            float* kd = Ksm + st_row * FL_LD + cq * 4;
            kd[0] = t32(kreg[t].x); kd[1] = t32(kreg[t].y);
            kd[2] = t32(kreg[t].z); kd[3] = t32(kreg[t].w);
            float* vd = Vsm + st_row * FL_LD + cq * 4;
            vd[0] = t32(vreg[t].x); vd[1] = t32(vreg[t].y);
            vd[2] = t32(vreg[t].z); vd[3] = t32(vreg[t].w);
        }
        __syncthreads();

        // S = Q * K^T  (warp computes its 16 rows x 64 cols; log2-domain scores)
        wmma::fragment<wmma::accumulator, 16, 16, 8, float> accS[4];
#pragma unroll
        for (int fn = 0; fn < 4; fn++) wmma::fill_fragment(accS[fn], 0.0f);
#pragma unroll
        for (int kk = 0; kk < 8; kk++) {
#pragma unroll
            for (int fn = 0; fn < 4; fn++) {
                wmma::fragment<wmma::matrix_b, 16, 16, 8, wmma::precision::tf32, wmma::col_major> kb;
                wmma::load_matrix_sync(kb, Ksm + (fn * 16) * FL_LD + kk * 8, FL_LD);
                wmma::mma_sync(accS[fn], qa[kk], kb, accS[fn]);
            }
        }
#pragma unroll
        for (int fn = 0; fn < 4; fn++)
            wmma::store_matrix_sync(Ssm + (w * 16) * FL_LD + fn * 16, accS[fn], FL_LD, wmma::mem_row_major);
        __syncwarp();

        // Online softmax (exp2 domain) on own row r; two lanes split 64 cols
        float* Sr = Ssm + r * FL_LD + ch * 32;
        float mx = -1e30f;
#pragma unroll
        for (int c = 0; c < 32; c++) mx = fmaxf(mx, Sr[c]);
        mx = fmaxf(mx, __shfl_xor_sync(0xffffffffu, mx, 1));
        const float m_new = fmaxf(m_run, mx);
        const float alpha = exp2f(m_run - m_new);
        float sum = 0.0f;
#pragma unroll
        for (int c = 0; c < 32; c++) {
            float p = exp2f(Sr[c] - m_new);
            Sr[c] = t32(p);
            sum += p;
        }
        sum += __shfl_xor_sync(0xffffffffu, sum, 1);
        l_run = l_run * alpha + sum;
        m_run = m_new;
        __syncwarp();

        // PV = P * V  (A = own P rows from Ssm, B = Vsm row_major [t][d])
        wmma::fragment<wmma::accumulator, 16, 16, 8, float> accO[4];
#pragma unroll
        for (int fn = 0; fn < 4; fn++) wmma::fill_fragment(accO[fn], 0.0f);
#pragma unroll
        for (int kk = 0; kk < 8; kk++) {
            wmma::fragment<wmma::matrix_a, 16, 16, 8, wmma::precision::tf32, wmma::row_major> pa;
            wmma::load_matrix_sync(pa, Ssm + (w * 16) * FL_LD + kk * 8, FL_LD);
#pragma unroll
            for (int fn = 0; fn < 4; fn++) {
                wmma::fragment<wmma::matrix_b, 16, 16, 8, wmma::precision::tf32, wmma::row_major> vb;
                wmma::load_matrix_sync(vb, Vsm + (kk * 8) * FL_LD + fn * 16, FL_LD);
                wmma::mma_sync(accO[fn], pa, vb, accO[fn]);
            }
        }
        __syncwarp();
#pragma unroll
        for (int fn = 0; fn < 4; fn++)
            wmma::store_matrix_sync(Ssm + (w * 16) * FL_LD + fn * 16, accO[fn], FL_LD, wmma::mem_row_major);
        __syncwarp();

        // O update (rescale + accumulate), warp-local rows
#pragma unroll
        for (int c = 0; c < 32; c++)
            O[c] = O[c] * alpha + Sr[c];
    }

    // Normalize and write context in [b][s][h*64+d] layout
    const float inv = 1.0f / l_run;
    const int s = s0 + r;
    const int b = bh / Hn, h = bh % Hn;
    float* op = g_ctx + ((size_t)b * Sn + s) * Dn + h * DKn + ch * 32;
#pragma unroll
    for (int c = 0; c < 32; c += 4) {
        float4 v4 = make_float4(O[c] * inv, O[c + 1] * inv, O[c + 2] * inv, O[c + 3] * inv);
        *(float4*)(op + c) = v4;
    }
}

// ---------------------------------------------------------------------------
// Launch
// ---------------------------------------------------------------------------
extern "C" void kernel_launch(void* const* d_in, const int* in_sizes, int n_in,
                              void* d_out, int out_size)
{
    (void)in_sizes; (void)n_in; (void)out_size;
    const float* x  = (const float*)d_in[0];
    const float* Wq = (const float*)d_in[1];
    const float* bq = (const float*)d_in[2];
    const float* Wk = (const float*)d_in[3];
    const float* bk = (const float*)d_in[4];
    const float* Wv = (const float*)d_in[5];
    const float* bv = (const float*)d_in[6];
    const float* Wo = (const float*)d_in[7];
    const float* bo = (const float*)d_in[8];
    float* out = (float*)d_out;

    cudaFuncSetAttribute(flash_kernel, cudaFuncAttributeMaxDynamicSharedMemorySize, FL_SMEM_BYTES);

    // Fused QKV: one launch, blockIdx.z selects the projection
    dim3 qkv_grid(Dn / 64, Mn / 128, 3);   // (12, 64, 3)
    proj_kernel<<<qkv_grid, 256>>>(x, Wq, bq, Wk, bk, Wv, bv, nullptr, 1);

    flash_kernel<<<dim3(Sn / FL_QT, Bn * Hn), 256, FL_SMEM_BYTES>>>();

    // Output projection from g_ctx
    dim3 ogrid(Dn / 64, Mn / 128, 1);
    proj_kernel<<<ogrid, 256>>>(nullptr, Wo, bo, nullptr, nullptr, nullptr, nullptr, out, 0);
}

// round 13
// speedup vs baseline: 1.1161x; 1.1161x over previous
#include <cuda_runtime.h>
#include <mma.h>

using namespace nvcuda;

// Problem constants
#define Bn   2
#define Sn   4096
#define Dn   768
#define Hn   12
#define DKn  64
#define Mn   (Bn * Sn)       // 8192 rows of the token matrix

// ---------------------------------------------------------------------------
// Scratch (allocation-free rule: __device__ globals)
// ---------------------------------------------------------------------------
__device__ float g_q[Bn * Hn * Sn * DKn];   // [b][h][s][d]
__device__ float g_k[Bn * Hn * Sn * DKn];
__device__ float g_v[Bn * Hn * Sn * DKn];
__device__ float g_ctx[Mn * Dn];            // [b][s][h*64+d] == [M][D] row-major

// TF32 round (rna) — explicit so both smem staging paths are consistent
__device__ __forceinline__ float t32(float x) {
    float y;
    asm("cvt.rna.tf32.f32 %0, %1;\n" : "=f"(y) : "f"(x));
    return y;
}

// ---------------------------------------------------------------------------
// Projection GEMM (unchanged — 437us QKV / ~146us O-proj measured round 9)
// ---------------------------------------------------------------------------
__global__ __launch_bounds__(256) void proj_kernel(
    const float* __restrict__ Xp,
    const float* __restrict__ W0, const float* __restrict__ b0,
    const float* __restrict__ W1, const float* __restrict__ b1,
    const float* __restrict__ W2, const float* __restrict__ b2,
    float* __restrict__ outp, int fused)
{
    __shared__ __align__(16) float sm[9216];     // 36.8 KB, reused by epilogue
    float* As = sm;               // 128 x 36 (K-tile 32, pad 4)
    float* Ws = sm + 128 * 36;    // 64 x 36

    const int z = fused ? blockIdx.z : 3;
    const float* X    = fused ? Xp : g_ctx;
    const float* W    = (z == 0) ? W0 : (z == 1) ? W1 : (z == 2) ? W2 : W0;
    const float* bias = (z == 0) ? b0 : (z == 1) ? b1 : (z == 2) ? b2 : b0;

    const int m0 = blockIdx.y * 128;
    const int n0 = blockIdx.x * 64;
    const int tid = threadIdx.x;
    const int wid = tid >> 5;
    const int lane = tid & 31;
    const int wm = wid & 3;       // warp row group (32 rows)
    const int wn = wid >> 2;      // warp col group (32 cols)

    wmma::fragment<wmma::accumulator, 16, 16, 8, float> acc[2][2];
#pragma unroll
    for (int i = 0; i < 2; i++)
#pragma unroll
        for (int j = 0; j < 2; j++)
            wmma::fill_fragment(acc[i][j], 0.0f);

    for (int k0 = 0; k0 < Dn; k0 += 32) {
        float4 av[4], wv[2];
#pragma unroll
        for (int t = 0; t < 4; t++) {
            int idx = tid + t * 256;
            int r = idx >> 3, kq = idx & 7;
            av[t] = *(const float4*)(X + (size_t)(m0 + r) * Dn + k0 + kq * 4);
        }
#pragma unroll
        for (int t = 0; t < 2; t++) {
            int idx = tid + t * 256;
            int r = idx >> 3, kq = idx & 7;
            wv[t] = *(const float4*)(W + (size_t)(n0 + r) * Dn + k0 + kq * 4);
        }
        __syncthreads();                         // prior iter's mma reads done
#pragma unroll
        for (int t = 0; t < 4; t++) {
            int idx = tid + t * 256;
            int r = idx >> 3, kq = idx & 7;
            float* d = As + r * 36 + kq * 4;
            d[0] = t32(av[t].x); d[1] = t32(av[t].y); d[2] = t32(av[t].z); d[3] = t32(av[t].w);
        }
#pragma unroll
        for (int t = 0; t < 2; t++) {
            int idx = tid + t * 256;
            int r = idx >> 3, kq = idx & 7;
            float* d = Ws + r * 36 + kq * 4;
            d[0] = t32(wv[t].x); d[1] = t32(wv[t].y); d[2] = t32(wv[t].z); d[3] = t32(wv[t].w);
        }
        __syncthreads();                         // tiles visible

#pragma unroll
        for (int kk = 0; kk < 4; kk++) {
            wmma::fragment<wmma::matrix_a, 16, 16, 8, wmma::precision::tf32, wmma::row_major> a[2];
            wmma::fragment<wmma::matrix_b, 16, 16, 8, wmma::precision::tf32, wmma::col_major> b[2];
#pragma unroll
            for (int i = 0; i < 2; i++)
                wmma::load_matrix_sync(a[i], As + (wm * 32 + i * 16) * 36 + kk * 8, 36);
#pragma unroll
            for (int j = 0; j < 2; j++)
                wmma::load_matrix_sync(b[j], Ws + (wn * 32 + j * 16) * 36 + kk * 8, 36);
#pragma unroll
            for (int i = 0; i < 2; i++)
#pragma unroll
                for (int j = 0; j < 2; j++)
                    wmma::mma_sync(acc[i][j], a[i], b[j], acc[i][j]);
        }
    }

    __syncthreads();
    float* csm = sm + wid * 32 * 36;
#pragma unroll
    for (int i = 0; i < 2; i++)
#pragma unroll
        for (int j = 0; j < 2; j++)
            wmma::store_matrix_sync(csm + (i * 16) * 36 + j * 16, acc[i][j], 36, wmma::mem_row_major);
    __syncwarp();

    const int gm_base = m0 + wm * 32;
    const int gn = n0 + wn * 32 + lane;           // lane-per-column -> coalesced
    const float bval = bias[gn];

    if (!fused) {
#pragma unroll 4
        for (int r = 0; r < 32; r++) {
            float val = csm[r * 36 + lane] + bval;
            outp[(size_t)(gm_base + r) * Dn + gn] = val;
        }
    } else {
        float* o = (z == 0) ? g_q : (z == 1) ? g_k : g_v;
        const int h = gn >> 6, d = gn & 63;       // 32-col slab never crosses a head
#pragma unroll 4
        for (int r = 0; r < 32; r++) {
            float val = csm[r * 36 + lane] + bval;
            int gm = gm_base + r;
            int b = gm >> 12, s = gm & 4095;
            o[(((size_t)b * Hn + h) * Sn + s) * DKn + d] = val;
        }
    }
}

// ---------------------------------------------------------------------------
// Flash attention: grid (S/128, B*H), block 256 (8 warps).
// Warp w owns rows [16w, 16w+16). Round-9 design (unbenched — resubmitted):
//  * Online softmax entirely IN REGISTERS on the accS fragments, using the
//    standard m16n16k8 f32 accumulator layout: lane l holds rows {l>>2,
//    (l>>2)+8}; x[0,1,4,5] = row l>>2, x[2,3,6,7] = row (l>>2)+8; each row's
//    16 cols per fragment live in the 4-lane quad -> shfl.xor 1,2 reduces.
//  * accO stays RESIDENT in accumulator fragments across all 64 KV tiles,
//    rescaled by per-row alpha in-register. No per-tile O smem traffic.
//  * Only P round-trips smem (acc layout != A-operand layout for tf32).
// Removes ~96 LDS + 64 STS per warp-tile vs round 8.
// ---------------------------------------------------------------------------
#define FL_QT 128                                 // queries per block
#define FL_LD 68                                  // 64 + 4 pad (multiple of 4)
#define FL_SMEM_BYTES ((2 * 64 + FL_QT) * FL_LD * (int)sizeof(float))  // 69632
#define QSCALE (0.125f * 1.4426950408889634f)     // (1/sqrt(64)) * log2(e)

__global__ __launch_bounds__(256) void flash_kernel()
{
    extern __shared__ float dsm[];
    float* Ksm = dsm;                    // [64][68], K tile, row-major [t][d]
    float* Vsm = dsm + 64 * FL_LD;       // [64][68], V tile, row-major [t][d]
    float* Ssm = dsm + 2 * 64 * FL_LD;   // [128][68], Q staging / P staging

    const int bh = blockIdx.y;                       // b*H + h
    const size_t base = (size_t)bh * Sn * DKn;
    const float* Q = g_q + base;
    const float* K = g_k + base;
    const float* V = g_v + base;
    const int s0 = blockIdx.x * FL_QT;

    const int tid = threadIdx.x;
    const int w = tid >> 5;
    const int lane = tid & 31;

    // Staging-loop thread->element map (shared by K and V): 4 float4 per thread
    const int st_row = tid >> 2;                     // 0..63   (tid/4)
    const int st_cq0 = (tid & 3) * 4;                // 0,4,8,12 (float4 index base)

    // Stage Q (pre-scaled into the exp2 domain) into Ssm, then preload A-frags.
#pragma unroll
    for (int t = 0; t < 8; t++) {
        int idx = tid + t * 256;
        int row = idx >> 4, cq = idx & 15;
        float4 v4 = *(const float4*)(Q + (size_t)(s0 + row) * DKn + cq * 4);
        float* d = Ssm + row * FL_LD + cq * 4;
        d[0] = t32(v4.x * QSCALE); d[1] = t32(v4.y * QSCALE);
        d[2] = t32(v4.z * QSCALE); d[3] = t32(v4.w * QSCALE);
    }
    __syncthreads();

    wmma::fragment<wmma::matrix_a, 16, 16, 8, wmma::precision::tf32, wmma::row_major> qa[8];
#pragma unroll
    for (int kk = 0; kk < 8; kk++)
        wmma::load_matrix_sync(qa[kk], Ssm + (w * 16) * FL_LD + kk * 8, FL_LD);

    // Running softmax state for this lane's two fragment rows (log2 domain).
    float m0 = -1e30f, m1 = -1e30f, l0 = 0.0f, l1 = 0.0f;
    wmma::fragment<wmma::accumulator, 16, 16, 8, float> accO[4];
#pragma unroll
    for (int fn = 0; fn < 4; fn++) wmma::fill_fragment(accO[fn], 0.0f);

    for (int j = 0; j < Sn / 64; j++) {
        const int t0 = j * 64;
        // --- Batched KV loads into registers (before the barrier) ---
        float4 kreg[4], vreg[4];
#pragma unroll
        for (int t = 0; t < 4; t++) {
            kreg[t] = *(const float4*)(K + (size_t)(t0 + st_row) * DKn + (st_cq0 + t) * 4);
            vreg[t] = *(const float4*)(V + (size_t)(t0 + st_row) * DKn + (st_cq0 + t) * 4);
        }
        __syncthreads();   // everyone done reading prior Ksm/Vsm/P (and iter-0 Q)
#pragma unroll
        for (int t = 0; t < 4; t++) {
            const int cq = st_cq0 + t;
            float* kd = Ksm + st_row * FL_LD + cq * 4;
            kd[0] = t32(kreg[t].x); kd[1] = t32(kreg[t].y);
            kd[2] = t32(kreg[t].z); kd[3] = t32(kreg[t].w);
            float* vd = Vsm + st_row * FL_LD + cq * 4;
            vd[0] = t32(vreg[t].x); vd[1] = t32(vreg[t].y);
            vd[2] = t32(vreg[t].z); vd[3] = t32(vreg[t].w);
        }
        __syncthreads();

        // S = Q * K^T  (warp computes its 16 rows x 64 cols; log2-domain scores)
        wmma::fragment<wmma::accumulator, 16, 16, 8, float> accS[4];
#pragma unroll
        for (int fn = 0; fn < 4; fn++) wmma::fill_fragment(accS[fn], 0.0f);
#pragma unroll
        for (int kk = 0; kk < 8; kk++) {
#pragma unroll
            for (int fn = 0; fn < 4; fn++) {
                wmma::fragment<wmma::matrix_b, 16, 16, 8, wmma::precision::tf32, wmma::col_major> kb;
                wmma::load_matrix_sync(kb, Ksm + (fn * 16) * FL_LD + kk * 8, FL_LD);
                wmma::mma_sync(accS[fn], qa[kk], kb, accS[fn]);
            }
        }

        // --- In-register online softmax on accS ---
        // Row A = this lane's fragment row (lane>>2): x[0,1,4,5]
        // Row B = (lane>>2)+8:                        x[2,3,6,7]
        float mx0 = -1e30f, mx1 = -1e30f;
#pragma unroll
        for (int fn = 0; fn < 4; fn++) {
            mx0 = fmaxf(mx0, fmaxf(fmaxf(accS[fn].x[0], accS[fn].x[1]),
                                   fmaxf(accS[fn].x[4], accS[fn].x[5])));
            mx1 = fmaxf(mx1, fmaxf(fmaxf(accS[fn].x[2], accS[fn].x[3]),
                                   fmaxf(accS[fn].x[6], accS[fn].x[7])));
        }
        mx0 = fmaxf(mx0, __shfl_xor_sync(0xffffffffu, mx0, 1));
        mx0 = fmaxf(mx0, __shfl_xor_sync(0xffffffffu, mx0, 2));
        mx1 = fmaxf(mx1, __shfl_xor_sync(0xffffffffu, mx1, 1));
        mx1 = fmaxf(mx1, __shfl_xor_sync(0xffffffffu, mx1, 2));

        const float m0n = fmaxf(m0, mx0);
        const float m1n = fmaxf(m1, mx1);
        const float a0 = exp2f(m0 - m0n);
        const float a1 = exp2f(m1 - m1n);

        float s0r = 0.0f, s1r = 0.0f;
#pragma unroll
        for (int fn = 0; fn < 4; fn++) {
            float p;
            p = exp2f(accS[fn].x[0] - m0n); s0r += p; accS[fn].x[0] = t32(p);
            p = exp2f(accS[fn].x[1] - m0n); s0r += p; accS[fn].x[1] = t32(p);
            p = exp2f(accS[fn].x[4] - m0n); s0r += p; accS[fn].x[4] = t32(p);
            p = exp2f(accS[fn].x[5] - m0n); s0r += p; accS[fn].x[5] = t32(p);
            p = exp2f(accS[fn].x[2] - m1n); s1r += p; accS[fn].x[2] = t32(p);
            p = exp2f(accS[fn].x[3] - m1n); s1r += p; accS[fn].x[3] = t32(p);
            p = exp2f(accS[fn].x[6] - m1n); s1r += p; accS[fn].x[6] = t32(p);
            p = exp2f(accS[fn].x[7] - m1n); s1r += p; accS[fn].x[7] = t32(p);
        }
        s0r += __shfl_xor_sync(0xffffffffu, s0r, 1);
        s0r += __shfl_xor_sync(0xffffffffu, s0r, 2);
        s1r += __shfl_xor_sync(0xffffffffu, s1r, 1);
        s1r += __shfl_xor_sync(0xffffffffu, s1r, 2);

        l0 = l0 * a0 + s0r;  m0 = m0n;
        l1 = l1 * a1 + s1r;  m1 = m1n;

        // Rescale resident accO by per-row alpha (same row mapping as accS)
#pragma unroll
        for (int fn = 0; fn < 4; fn++) {
            accO[fn].x[0] *= a0; accO[fn].x[1] *= a0;
            accO[fn].x[4] *= a0; accO[fn].x[5] *= a0;
            accO[fn].x[2] *= a1; accO[fn].x[3] *= a1;
            accO[fn].x[6] *= a1; accO[fn].x[7] *= a1;
        }

        // P -> smem (A-operand layout differs from acc layout for tf32)
#pragma unroll
        for (int fn = 0; fn < 4; fn++)
            wmma::store_matrix_sync(Ssm + (w * 16) * FL_LD + fn * 16, accS[fn], FL_LD, wmma::mem_row_major);
        __syncwarp();

        // PV accumulates straight into resident accO
#pragma unroll
        for (int kk = 0; kk < 8; kk++) {
            wmma::fragment<wmma::matrix_a, 16, 16, 8, wmma::precision::tf32, wmma::row_major> pa;
            wmma::load_matrix_sync(pa, Ssm + (w * 16) * FL_LD + kk * 8, FL_LD);
#pragma unroll
            for (int fn = 0; fn < 4; fn++) {
                wmma::fragment<wmma::matrix_b, 16, 16, 8, wmma::precision::tf32, wmma::row_major> vb;
                wmma::load_matrix_sync(vb, Vsm + (kk * 8) * FL_LD + fn * 16, FL_LD);
                wmma::mma_sync(accO[fn], pa, vb, accO[fn]);
            }
        }
        // next iteration's staging __syncthreads orders Ssm reuse
    }

    // Normalize in-register, park in smem, write coalesced.
    const float inv0 = 1.0f / l0;
    const float inv1 = 1.0f / l1;
#pragma unroll
    for (int fn = 0; fn < 4; fn++) {
        accO[fn].x[0] *= inv0; accO[fn].x[1] *= inv0;
        accO[fn].x[4] *= inv0; accO[fn].x[5] *= inv0;
        accO[fn].x[2] *= inv1; accO[fn].x[3] *= inv1;
        accO[fn].x[6] *= inv1; accO[fn].x[7] *= inv1;
    }
#pragma unroll
    for (int fn = 0; fn < 4; fn++)
        wmma::store_matrix_sync(Ssm + (w * 16) * FL_LD + fn * 16, accO[fn], FL_LD, wmma::mem_row_major);
    __syncwarp();

    const int r = w * 16 + (lane >> 1);              // row in this warp's block
    const int ch = lane & 1;                         // column half
    const int s = s0 + r;
    const int b = bh / Hn, h = bh % Hn;
    float* op = g_ctx + ((size_t)b * Sn + s) * Dn + h * DKn + ch * 32;
    const float* src = Ssm + r * FL_LD + ch * 32;
#pragma unroll
    for (int c = 0; c < 32; c += 4)
        *(float4*)(op + c) = *(const float4*)(src + c);
}

// ---------------------------------------------------------------------------
// Launch
// ---------------------------------------------------------------------------
extern "C" void kernel_launch(void* const* d_in, const int* in_sizes, int n_in,
                              void* d_out, int out_size)
{
    (void)in_sizes; (void)n_in; (void)out_size;
    const float* x  = (const float*)d_in[0];
    const float* Wq = (const float*)d_in[1];
    const float* bq = (const float*)d_in[2];
    const float* Wk = (const float*)d_in[3];
    const float* bk = (const float*)d_in[4];
    const float* Wv = (const float*)d_in[5];
    const float* bv = (const float*)d_in[6];
    const float* Wo = (const float*)d_in[7];
    const float* bo = (const float*)d_in[8];
    float* out = (float*)d_out;

    cudaFuncSetAttribute(flash_kernel, cudaFuncAttributeMaxDynamicSharedMemorySize, FL_SMEM_BYTES);

    // Fused QKV: one launch, blockIdx.z selects the projection
    dim3 qkv_grid(Dn / 64, Mn / 128, 3);   // (12, 64, 3)
    proj_kernel<<<qkv_grid, 256>>>(x, Wq, bq, Wk, bk, Wv, bv, nullptr, 1);

    flash_kernel<<<dim3(Sn / FL_QT, Bn * Hn), 256, FL_SMEM_BYTES>>>();

    // Output projection from g_ctx
    dim3 ogrid(Dn / 64, Mn / 128, 1);
    proj_kernel<<<ogrid, 256>>>(nullptr, Wo, bo, nullptr, nullptr, nullptr, nullptr, out, 0);
}